// round 4
// baseline (speedup 1.0000x reference)
#include <cuda_runtime.h>
#include <math.h>

#define Bc 4
#define Nc 5
#define Cc 64
#define Hc 96
#define Wc 288
#define HWc (Hc * Wc)

// DECAY_WEIGHTS = softmax([1.0, 0.5])
#define W0c 0.6224593312018546f
#define W1c 0.3775406687981454f

// score kernel tiling
#define SPX 32
#define SCG 16
#define SCPT 4

// fuse kernel tiling
#define FPX 32
#define FCG 32
#define FCPT 2

__device__ float g_theta[Bc * Nc * 6];
__device__ float g_mask[Bc * HWc];
__device__ float g_dmask[Bc * HWc];

// ---------------------------------------------------------------------------
// Kernel T: build 2x3 affine thetas from pairwise_t_matrix[b, 0, n]
// ---------------------------------------------------------------------------
__global__ void theta_kernel(const float* __restrict__ pt) {
    int t = threadIdx.x;
    if (t >= Bc * Nc) return;
    int b = t / Nc, n = t % Nc;
    const float* P = pt + ((size_t)(b * Nc + 0) * Nc + n) * 16;  // 4x4 row-major
    float* th = g_theta + t * 6;
    th[0] = P[0];
    th[1] = P[1] * ((float)Hc / (float)Wc);
    th[2] = P[3] / (4.0f * 0.4f * (float)Wc) * 2.0f;
    th[3] = P[4] * ((float)Wc / (float)Hc);
    th[4] = P[5];
    th[5] = P[7] / (4.0f * 0.4f * (float)Hc) * 2.0f;
}

// ---------------------------------------------------------------------------
// Kernel A: per-pixel confidence -> binary mask (one batch per launch)
// ---------------------------------------------------------------------------
__global__ __launch_bounds__(SPX * SCG)
void score_kernel(const float* __restrict__ x0, const float* __restrict__ x1,
                  const float* __restrict__ mlp_w, const float* __restrict__ mlp_b,
                  int b) {
    __shared__ float sm_ss[2][4][SCG][SPX];
    __shared__ float sm_mm[2][4][SCG][SPX];

    int tx = threadIdx.x;
    int ty = threadIdx.y;
    int p  = blockIdx.x * SPX + tx;
    int c0 = ty * SCPT;

    float w[SCPT];
    #pragma unroll
    for (int cc = 0; cc < SCPT; cc++) w[cc] = __ldg(mlp_w + c0 + cc);

    #pragma unroll
    for (int f = 0; f < 2; f++) {
        const float* xf = (f == 0) ? x0 : x1;
        const float* base = xf + (size_t)b * Nc * Cc * HWc + (size_t)c0 * HWc + p;

        float e[SCPT];
        #pragma unroll
        for (int cc = 0; cc < SCPT; cc++) e[cc] = base[(size_t)cc * HWc];

        #pragma unroll
        for (int k = 0; k < 4; k++) {
            const float* nb = base + (size_t)(k + 1) * Cc * HWc;
            float ss = 0.f, mm = 0.f;
            #pragma unroll
            for (int cc = 0; cc < SCPT; cc++) {
                float v = nb[(size_t)cc * HWc];
                ss = fmaf(e[cc], v, ss);
                mm = fmaf(w[cc], v, mm);
            }
            sm_ss[f][k][ty][tx] = ss;
            sm_mm[f][k][ty][tx] = mm;
        }
    }
    __syncthreads();

    if (ty == 0) {
        float bb = __ldg(mlp_b);
        float conf = 0.f;
        const float dw[2] = {W0c, W1c};
        #pragma unroll
        for (int f = 0; f < 2; f++) {
            float s[4], m[4];
            #pragma unroll
            for (int k = 0; k < 4; k++) {
                float ss = 0.f, mm = 0.f;
                #pragma unroll
                for (int cg = 0; cg < SCG; cg++) {
                    ss += sm_ss[f][k][cg][tx];
                    mm += sm_mm[f][k][cg][tx];
                }
                s[k] = ss * 0.125f;
                m[k] = mm;
            }
            float mx = fmaxf(fmaxf(s[0], s[1]), fmaxf(s[2], s[3]));
            float sum = 0.f, acc = 0.f;
            #pragma unroll
            for (int k = 0; k < 4; k++) {
                float e2 = expf(s[k] - mx);
                sum += e2;
                acc = fmaf(e2, m[k], acc);
            }
            float z = acc / sum + bb;
            conf += dw[f] / (1.f + expf(-z));
        }
        g_mask[b * HWc + p] = (conf > 0.5f) ? 1.0f : 0.0f;
    }
}

// ---------------------------------------------------------------------------
// Kernel B: 3x3 max dilation (SAME), one batch per launch
// ---------------------------------------------------------------------------
__global__ void dilate_kernel(int b) {
    int p = blockIdx.x * blockDim.x + threadIdx.x;
    if (p >= HWc) return;
    int i = p / Wc, j = p % Wc;
    float m = 0.f;
    #pragma unroll
    for (int di = -1; di <= 1; di++) {
        int ii = i + di;
        if (ii < 0 || ii >= Hc) continue;
        #pragma unroll
        for (int dj = -1; dj <= 1; dj++) {
            int jj = j + dj;
            if (jj < 0 || jj >= Wc) continue;
            m = fmaxf(m, g_mask[b * HWc + ii * Wc + jj]);
        }
    }
    g_dmask[b * HWc + p] = m;
}

// ---------------------------------------------------------------------------
// Kernel C: warp + 5-way attention fusion (one batch per launch)
//   taps in smem packed as float4 / int2; weights fold validity + mask
// ---------------------------------------------------------------------------
__global__ __launch_bounds__(FPX * FCG, 2)
void fuse_kernel(const float* __restrict__ x0, float* __restrict__ out, int b) {
    __shared__ float  sm_s[Nc][FCG][FPX];    // score partials
    __shared__ float  sm_red[Nc][FPX];       // reduced scores
    __shared__ float4 sm_w[Nc][FPX];         // packed tap weights
    __shared__ int2   sm_bi[Nc][FPX];        // packed row bases

    int tx = threadIdx.x;
    int ty = threadIdx.y;
    int p  = blockIdx.x * FPX + tx;
    int tid = ty * FPX + tx;

    // ---- tap precompute: one thread per (frame, pixel) ----
    if (tid < Nc * FPX) {
        int n  = tid / FPX;
        int lx = tid - n * FPX;
        int pp = blockIdx.x * FPX + lx;
        int i = pp / Wc, j = pp - i * Wc;
        float gx = -1.f + 2.f * (float)j / (float)(Wc - 1);
        float gy = -1.f + 2.f * (float)i / (float)(Hc - 1);

        const float* th = g_theta + (b * Nc + n) * 6;
        float g0 = fmaf(th[0], gx, fmaf(th[1], gy, th[2]));
        float g1 = fmaf(th[3], gx, fmaf(th[4], gy, th[5]));
        float pxf = (g0 + 1.f) * 0.5f * (float)(Wc - 1);
        float pyf = (g1 + 1.f) * 0.5f * (float)(Hc - 1);
        float x0f = floorf(pxf), y0f = floorf(pyf);
        float wx = pxf - x0f, wy = pyf - y0f;
        int xi = (int)x0f, yi = (int)y0f;

        int r0 = min(max(yi, 0), Hc - 1) * Wc;
        int r1 = min(max(yi + 1, 0), Hc - 1) * Wc;
        float wy0 = (yi >= 0 && yi <= Hc - 1) ? (1.f - wy) : 0.f;
        float wy1 = (yi + 1 >= 0 && yi + 1 <= Hc - 1) ? wy : 0.f;

        int bx = min(max(xi, 0), Wc - 2);
        int sh = xi - bx;
        float ax0, ax1;
        if (sh == 0)        { ax0 = 1.f - wx; ax1 = wx;       }
        else if (sh == -1)  { ax0 = wx;       ax1 = 0.f;      }
        else if (sh == 1)   { ax0 = 0.f;      ax1 = 1.f - wx; }
        else                { ax0 = 0.f;      ax1 = 0.f;      }

        float m00 = 1.f, m01 = 1.f, m10 = 1.f, m11 = 1.f;
        if (n > 0) {
            const float* dm = g_dmask + b * HWc;
            m00 = dm[r0 + bx]; m01 = dm[r0 + bx + 1];
            m10 = dm[r1 + bx]; m11 = dm[r1 + bx + 1];
        }

        sm_bi[n][lx] = make_int2(r0 + bx, r1 + bx);
        sm_w[n][lx]  = make_float4(ax0 * wy0 * m00, ax1 * wy0 * m01,
                                   ax0 * wy1 * m10, ax1 * wy1 * m11);
    }
    __syncthreads();

    // ---- gather + score partials ----
    const float* xb = x0 + (size_t)b * Nc * Cc * HWc + (size_t)(ty * FCPT) * HWc;

    float v[Nc][FCPT];
    #pragma unroll
    for (int k = 0; k < Nc; k++) {
        int2   bi = sm_bi[k][tx];
        float4 w  = sm_w[k][tx];
        const float* imgb = xb + (size_t)k * Cc * HWc;
        float ss = 0.f;
        #pragma unroll
        for (int cc = 0; cc < FCPT; cc++) {
            const float* im = imgb + (size_t)cc * HWc;
            float val = fmaf(w.x, __ldg(im + bi.x),
                        fmaf(w.y, __ldg(im + bi.x + 1),
                        fmaf(w.z, __ldg(im + bi.y),
                             w.w * __ldg(im + bi.y + 1))));
            v[k][cc] = val;
            ss = fmaf(v[0][cc], val, ss);   // k==0: val*val
        }
        sm_s[k][ty][tx] = ss;
    }
    __syncthreads();

    // ---- parallel reduction: warp k reduces frame k ----
    if (ty < Nc) {
        float ssum = 0.f;
        #pragma unroll
        for (int cg = 0; cg < FCG; cg++) ssum += sm_s[ty][cg][tx];
        sm_red[ty][tx] = ssum * 0.125f;
    }
    __syncthreads();

    // ---- per-thread softmax (redundant, cheap) + fuse + store ----
    float s[Nc];
    #pragma unroll
    for (int k = 0; k < Nc; k++) s[k] = sm_red[k][tx];
    float mx = s[0];
    #pragma unroll
    for (int k = 1; k < Nc; k++) mx = fmaxf(mx, s[k]);
    float a[Nc], sum = 0.f;
    #pragma unroll
    for (int k = 0; k < Nc; k++) { a[k] = __expf(s[k] - mx); sum += a[k]; }
    float inv = 1.f / sum;

    int c0 = ty * FCPT;
    #pragma unroll
    for (int cc = 0; cc < FCPT; cc++) {
        float o = 0.f;
        #pragma unroll
        for (int k = 0; k < Nc; k++) o = fmaf(a[k], v[k][cc], o);
        out[((size_t)b * Cc + c0 + cc) * HWc + p] = o * inv;
    }
}

// ---------------------------------------------------------------------------
// Launch: per-batch pipeline so fuse(b) hits x0[b] in L2 right after score(b)
// ---------------------------------------------------------------------------
extern "C" void kernel_launch(void* const* d_in, const int* in_sizes, int n_in,
                              void* d_out, int out_size) {
    const float* x0    = (const float*)d_in[0];
    const float* x1    = (const float*)d_in[1];
    const float* pt    = (const float*)d_in[2];
    const float* mlp_w = (const float*)d_in[3];
    const float* mlp_b = (const float*)d_in[4];
    float* out = (float*)d_out;

    theta_kernel<<<1, 32>>>(pt);

    dim3 blkS(SPX, SCG);
    dim3 blkF(FPX, FCG);
    int gridS = HWc / SPX;
    int gridF = HWc / FPX;
    int gridD = (HWc + 255) / 256;

    for (int b = 0; b < Bc; b++) {
        score_kernel<<<gridS, blkS>>>(x0, x1, mlp_w, mlp_b, b);
        dilate_kernel<<<gridD, 256>>>(b);
        fuse_kernel<<<gridF, blkF>>>(x0, out, b);
    }
}

// round 5
// speedup vs baseline: 1.2288x; 1.2288x over previous
#include <cuda_runtime.h>
#include <math.h>

#define Bc 4
#define Nc 5
#define Cc 64
#define Hc 96
#define Wc 288
#define HWc (Hc * Wc)

// DECAY_WEIGHTS = softmax([1.0, 0.5])
#define W0c 0.6224593312018546f
#define W1c 0.3775406687981454f

// score kernel tiling
#define SPX 32
#define SCG 16
#define SCPT 4

// fuse kernel tiling
#define FPX 32
#define FCG 16
#define FCPT 4

__device__ float g_theta[Bc * Nc * 6];
__device__ float g_mask[Bc * HWc];
__device__ float g_dmask[Bc * HWc];

// ---------------------------------------------------------------------------
// Kernel T: build 2x3 affine thetas from pairwise_t_matrix[b, 0, n]
// ---------------------------------------------------------------------------
__global__ void theta_kernel(const float* __restrict__ pt) {
    int t = threadIdx.x;
    if (t >= Bc * Nc) return;
    int b = t / Nc, n = t % Nc;
    const float* P = pt + ((size_t)(b * Nc + 0) * Nc + n) * 16;  // 4x4 row-major
    float* th = g_theta + t * 6;
    th[0] = P[0];
    th[1] = P[1] * ((float)Hc / (float)Wc);
    th[2] = P[3] / (4.0f * 0.4f * (float)Wc) * 2.0f;
    th[3] = P[4] * ((float)Wc / (float)Hc);
    th[4] = P[5];
    th[5] = P[7] / (4.0f * 0.4f * (float)Hc) * 2.0f;
}

// ---------------------------------------------------------------------------
// Kernel A: per-pixel confidence -> binary mask (all batches)
// ---------------------------------------------------------------------------
__global__ __launch_bounds__(SPX * SCG)
void score_kernel(const float* __restrict__ x0, const float* __restrict__ x1,
                  const float* __restrict__ mlp_w, const float* __restrict__ mlp_b) {
    __shared__ float sm_ss[2][4][SCG][SPX];
    __shared__ float sm_mm[2][4][SCG][SPX];

    int tx = threadIdx.x;
    int ty = threadIdx.y;
    int p  = blockIdx.x * SPX + tx;
    int b  = blockIdx.y;
    int c0 = ty * SCPT;

    float w[SCPT];
    #pragma unroll
    for (int cc = 0; cc < SCPT; cc++) w[cc] = __ldg(mlp_w + c0 + cc);

    #pragma unroll
    for (int f = 0; f < 2; f++) {
        const float* xf = (f == 0) ? x0 : x1;
        const float* base = xf + (size_t)b * Nc * Cc * HWc + (size_t)c0 * HWc + p;

        float e[SCPT];
        #pragma unroll
        for (int cc = 0; cc < SCPT; cc++) e[cc] = base[(size_t)cc * HWc];

        #pragma unroll
        for (int k = 0; k < 4; k++) {
            const float* nb = base + (size_t)(k + 1) * Cc * HWc;
            float ss = 0.f, mm = 0.f;
            #pragma unroll
            for (int cc = 0; cc < SCPT; cc++) {
                float v = nb[(size_t)cc * HWc];
                ss = fmaf(e[cc], v, ss);
                mm = fmaf(w[cc], v, mm);
            }
            sm_ss[f][k][ty][tx] = ss;
            sm_mm[f][k][ty][tx] = mm;
        }
    }
    __syncthreads();

    if (ty == 0) {
        float bb = __ldg(mlp_b);
        float conf = 0.f;
        const float dw[2] = {W0c, W1c};
        #pragma unroll
        for (int f = 0; f < 2; f++) {
            float s[4], m[4];
            #pragma unroll
            for (int k = 0; k < 4; k++) {
                float ss = 0.f, mm = 0.f;
                #pragma unroll
                for (int cg = 0; cg < SCG; cg++) {
                    ss += sm_ss[f][k][cg][tx];
                    mm += sm_mm[f][k][cg][tx];
                }
                s[k] = ss * 0.125f;
                m[k] = mm;
            }
            float mx = fmaxf(fmaxf(s[0], s[1]), fmaxf(s[2], s[3]));
            float sum = 0.f, acc = 0.f;
            #pragma unroll
            for (int k = 0; k < 4; k++) {
                float e2 = expf(s[k] - mx);
                sum += e2;
                acc = fmaf(e2, m[k], acc);
            }
            float z = acc / sum + bb;
            conf += dw[f] / (1.f + expf(-z));
        }
        g_mask[b * HWc + p] = (conf > 0.5f) ? 1.0f : 0.0f;
    }
}

// ---------------------------------------------------------------------------
// Kernel B: 3x3 max dilation (SAME), all batches
// ---------------------------------------------------------------------------
__global__ void dilate_kernel() {
    int p = blockIdx.x * blockDim.x + threadIdx.x;
    int b = blockIdx.y;
    if (p >= HWc) return;
    int i = p / Wc, j = p % Wc;
    float m = 0.f;
    #pragma unroll
    for (int di = -1; di <= 1; di++) {
        int ii = i + di;
        if (ii < 0 || ii >= Hc) continue;
        #pragma unroll
        for (int dj = -1; dj <= 1; dj++) {
            int jj = j + dj;
            if (jj < 0 || jj >= Wc) continue;
            m = fmaxf(m, g_mask[b * HWc + ii * Wc + jj]);
        }
    }
    g_dmask[b * HWc + p] = m;
}

// ---------------------------------------------------------------------------
// Kernel C: warp + 5-way attention fusion (all batches)
//   512 threads, 4 channels/thread -> 16 independent LDGs per frame,
//   3 blocks/SM (75% occ, <=42 regs)
// ---------------------------------------------------------------------------
__global__ __launch_bounds__(FPX * FCG, 3)
void fuse_kernel(const float* __restrict__ x0, float* __restrict__ out) {
    __shared__ float  sm_s[Nc][FCG][FPX];    // score partials
    __shared__ float  sm_red[Nc][FPX];       // reduced scores
    __shared__ float4 sm_w[Nc][FPX];         // packed tap weights
    __shared__ int2   sm_bi[Nc][FPX];        // packed row bases

    int tx = threadIdx.x;
    int ty = threadIdx.y;
    int p  = blockIdx.x * FPX + tx;
    int b  = blockIdx.y;
    int tid = ty * FPX + tx;

    // ---- tap precompute: one thread per (frame, pixel) ----
    if (tid < Nc * FPX) {
        int n  = tid / FPX;
        int lx = tid - n * FPX;
        int pp = blockIdx.x * FPX + lx;
        int i = pp / Wc, j = pp - i * Wc;
        float gx = -1.f + 2.f * (float)j / (float)(Wc - 1);
        float gy = -1.f + 2.f * (float)i / (float)(Hc - 1);

        const float* th = g_theta + (b * Nc + n) * 6;
        float g0 = fmaf(th[0], gx, fmaf(th[1], gy, th[2]));
        float g1 = fmaf(th[3], gx, fmaf(th[4], gy, th[5]));
        float pxf = (g0 + 1.f) * 0.5f * (float)(Wc - 1);
        float pyf = (g1 + 1.f) * 0.5f * (float)(Hc - 1);
        float x0f = floorf(pxf), y0f = floorf(pyf);
        float wx = pxf - x0f, wy = pyf - y0f;
        int xi = (int)x0f, yi = (int)y0f;

        int r0 = min(max(yi, 0), Hc - 1) * Wc;
        int r1 = min(max(yi + 1, 0), Hc - 1) * Wc;
        float wy0 = (yi >= 0 && yi <= Hc - 1) ? (1.f - wy) : 0.f;
        float wy1 = (yi + 1 >= 0 && yi + 1 <= Hc - 1) ? wy : 0.f;

        int bx = min(max(xi, 0), Wc - 2);
        int sh = xi - bx;
        float ax0, ax1;
        if (sh == 0)        { ax0 = 1.f - wx; ax1 = wx;       }
        else if (sh == -1)  { ax0 = wx;       ax1 = 0.f;      }
        else if (sh == 1)   { ax0 = 0.f;      ax1 = 1.f - wx; }
        else                { ax0 = 0.f;      ax1 = 0.f;      }

        float m00 = 1.f, m01 = 1.f, m10 = 1.f, m11 = 1.f;
        if (n > 0) {
            const float* dm = g_dmask + b * HWc;
            m00 = dm[r0 + bx]; m01 = dm[r0 + bx + 1];
            m10 = dm[r1 + bx]; m11 = dm[r1 + bx + 1];
        }

        sm_bi[n][lx] = make_int2(r0 + bx, r1 + bx);
        sm_w[n][lx]  = make_float4(ax0 * wy0 * m00, ax1 * wy0 * m01,
                                   ax0 * wy1 * m10, ax1 * wy1 * m11);
    }
    __syncthreads();

    // ---- gather + score partials ----
    const float* xb = x0 + (size_t)b * Nc * Cc * HWc + (size_t)(ty * FCPT) * HWc;

    float v[Nc][FCPT];
    #pragma unroll
    for (int k = 0; k < Nc; k++) {
        int2   bi = sm_bi[k][tx];
        float4 w  = sm_w[k][tx];
        const float* im0 = xb + (size_t)k * Cc * HWc + bi.x;
        const float* im1 = xb + (size_t)k * Cc * HWc + bi.y;
        float ss = 0.f;
        #pragma unroll
        for (int cc = 0; cc < FCPT; cc++) {
            size_t off = (size_t)cc * HWc;
            float val = fmaf(w.x, __ldg(im0 + off),
                        fmaf(w.y, __ldg(im0 + off + 1),
                        fmaf(w.z, __ldg(im1 + off),
                             w.w * __ldg(im1 + off + 1))));
            v[k][cc] = val;
            ss = fmaf(v[0][cc], val, ss);   // k==0: val*val
        }
        sm_s[k][ty][tx] = ss;
    }
    __syncthreads();

    // ---- parallel reduction: warp k reduces frame k ----
    if (ty < Nc) {
        float ssum = 0.f;
        #pragma unroll
        for (int cg = 0; cg < FCG; cg++) ssum += sm_s[ty][cg][tx];
        sm_red[ty][tx] = ssum * 0.125f;
    }
    __syncthreads();

    // ---- per-thread softmax (redundant, cheap) + fuse + store ----
    float s[Nc];
    #pragma unroll
    for (int k = 0; k < Nc; k++) s[k] = sm_red[k][tx];
    float mx = s[0];
    #pragma unroll
    for (int k = 1; k < Nc; k++) mx = fmaxf(mx, s[k]);
    float a[Nc], sum = 0.f;
    #pragma unroll
    for (int k = 0; k < Nc; k++) { a[k] = __expf(s[k] - mx); sum += a[k]; }
    float inv = 1.f / sum;

    int c0 = ty * FCPT;
    #pragma unroll
    for (int cc = 0; cc < FCPT; cc++) {
        float o = 0.f;
        #pragma unroll
        for (int k = 0; k < Nc; k++) o = fmaf(a[k], v[k][cc], o);
        out[((size_t)b * Cc + c0 + cc) * HWc + p] = o * inv;
    }
}

// ---------------------------------------------------------------------------
// Launch
// ---------------------------------------------------------------------------
extern "C" void kernel_launch(void* const* d_in, const int* in_sizes, int n_in,
                              void* d_out, int out_size) {
    const float* x0    = (const float*)d_in[0];
    const float* x1    = (const float*)d_in[1];
    const float* pt    = (const float*)d_in[2];
    const float* mlp_w = (const float*)d_in[3];
    const float* mlp_b = (const float*)d_in[4];
    float* out = (float*)d_out;

    theta_kernel<<<1, 32>>>(pt);

    dim3 blkS(SPX, SCG);
    dim3 gridS(HWc / SPX, Bc);
    score_kernel<<<gridS, blkS>>>(x0, x1, mlp_w, mlp_b);

    dim3 gridB((HWc + 255) / 256, Bc);
    dilate_kernel<<<gridB, 256>>>();

    dim3 blkF(FPX, FCG);
    dim3 gridF(HWc / FPX, Bc);
    fuse_kernel<<<gridF, blkF>>>(x0, out);
}